// round 6
// baseline (speedup 1.0000x reference)
#include <cuda_runtime.h>

// Shapes: x (16,256,4096), w_qkv (768,256), w_out (256,256), b_out (256)
__device__ float g_kv[16LL * 512 * 4096];   // k (rows 0..255) and v (rows 256..511) per batch
__device__ float g_ctx[16 * 4 * 64 * 64];   // UNNORMALIZED context per (b, h)
__device__ float g_w2[16 * 256 * 256];      // fused (w_out x ctx / ksum) per batch
__device__ float g_ksum[16 * 256];          // per k-row sum of exp(k)

__device__ __forceinline__ unsigned f2tf32(float f) {
    unsigned u; asm("cvt.rna.tf32.f32 %0, %1;" : "=r"(u) : "f"(f)); return u;
}

__device__ __forceinline__ void mma8(float* c, const unsigned* a, const unsigned* b) {
    asm volatile(
        "mma.sync.aligned.m16n8k8.row.col.f32.tf32.tf32.f32 "
        "{%0,%1,%2,%3},{%4,%5,%6,%7},{%8,%9},{%0,%1,%2,%3};"
        : "+f"(c[0]), "+f"(c[1]), "+f"(c[2]), "+f"(c[3])
        : "r"(a[0]), "r"(a[1]), "r"(a[2]), "r"(a[3]), "r"(b[0]), "r"(b[1]));
}

#define SA 136

// ---------------------------------------------------------------------------
// TF32 GEMM for k,v: C[b] = A(M x K, lda) @ B[b](K x 4096)
// 128x128 tile, BK=16, double-buffered, 8 warps (2x4) of 64x32.
// ---------------------------------------------------------------------------
__global__ __launch_bounds__(256) void gemm_tf32_kernel(
    const float* __restrict__ A, long long strideA, int lda,
    const float* __restrict__ B, long long strideB,
    float* __restrict__ C, long long strideC, int Kdim)
{
    const int NN = 4096;
    const int n0 = blockIdx.x * 128;
    const int m0 = blockIdx.y * 128;
    const long long bz = blockIdx.z;
    A += bz * strideA;  B += bz * strideB;  C += bz * strideC;

    __shared__ unsigned As[2][16][SA];
    __shared__ unsigned Bs[2][16][SA];

    const int tid  = threadIdx.x;
    const int lane = tid & 31, warp = tid >> 5;
    const int wm = warp >> 2, wn = warp & 3;
    const int g  = lane >> 2, tig = lane & 3;

    const int arow = tid >> 2, ac = tid & 3;
    const int brow = tid >> 5, bn = (tid & 31) * 4;

    float acc[4][4][4];
    #pragma unroll
    for (int i = 0; i < 4; i++)
        #pragma unroll
        for (int j = 0; j < 4; j++)
            #pragma unroll
            for (int k = 0; k < 4; k++) acc[i][j][k] = 0.f;

    const float* Ap = A + (long long)m0 * lda;
    float4 av[2], bv[2];
    #pragma unroll
    for (int i = 0; i < 2; i++) {
        av[i] = *(const float4*)(Ap + (long long)(arow + 64 * i) * lda + ac * 4);
        bv[i] = *(const float4*)(B + (long long)(brow + 8 * i) * NN + n0 + bn);
    }
    #pragma unroll
    for (int i = 0; i < 2; i++) {
        const int r = (arow + 64 * i) ^ (ac << 3);
        As[0][4 * ac + 0][r] = f2tf32(av[i].x);
        As[0][4 * ac + 1][r] = f2tf32(av[i].y);
        As[0][4 * ac + 2][r] = f2tf32(av[i].z);
        As[0][4 * ac + 3][r] = f2tf32(av[i].w);
        const int br = brow + 8 * i;
        Bs[0][br][bn + 0] = f2tf32(bv[i].x);
        Bs[0][br][bn + 1] = f2tf32(bv[i].y);
        Bs[0][br][bn + 2] = f2tf32(bv[i].z);
        Bs[0][br][bn + 3] = f2tf32(bv[i].w);
    }
    __syncthreads();

    for (int k0 = 0; ; k0 += 16) {
        const int cur = (k0 >> 4) & 1;
        const bool more = (k0 + 16 < Kdim);
        if (more) {
            const int k1 = k0 + 16;
            #pragma unroll
            for (int i = 0; i < 2; i++) {
                av[i] = *(const float4*)(Ap + (long long)(arow + 64 * i) * lda + k1 + ac * 4);
                bv[i] = *(const float4*)(B + (long long)(k1 + brow + 8 * i) * NN + n0 + bn);
            }
        }

        #pragma unroll
        for (int kk = 0; kk < 16; kk += 8) {
            unsigned a[4][4], bf[4][2];
            const int xr  = (kk >> 2) << 3;
            const int xr2 = xr + 8;
            #pragma unroll
            for (int mt = 0; mt < 4; mt++) {
                const int m = wm * 64 + mt * 16 + g;
                a[mt][0] = As[cur][kk + tig    ][m       ^ xr ];
                a[mt][1] = As[cur][kk + tig    ][(m + 8) ^ xr ];
                a[mt][2] = As[cur][kk + tig + 4][m       ^ xr2];
                a[mt][3] = As[cur][kk + tig + 4][(m + 8) ^ xr2];
            }
            #pragma unroll
            for (int nt = 0; nt < 4; nt++) {
                const int n = wn * 32 + nt * 8 + g;
                bf[nt][0] = Bs[cur][kk + tig    ][n];
                bf[nt][1] = Bs[cur][kk + tig + 4][n];
            }
            #pragma unroll
            for (int mt = 0; mt < 4; mt++)
                #pragma unroll
                for (int nt = 0; nt < 4; nt++)
                    mma8(acc[mt][nt], a[mt], bf[nt]);
        }

        if (!more) break;

        const int nxt = cur ^ 1;
        #pragma unroll
        for (int i = 0; i < 2; i++) {
            const int r = (arow + 64 * i) ^ (ac << 3);
            As[nxt][4 * ac + 0][r] = f2tf32(av[i].x);
            As[nxt][4 * ac + 1][r] = f2tf32(av[i].y);
            As[nxt][4 * ac + 2][r] = f2tf32(av[i].z);
            As[nxt][4 * ac + 3][r] = f2tf32(av[i].w);
            const int br = brow + 8 * i;
            Bs[nxt][br][bn + 0] = f2tf32(bv[i].x);
            Bs[nxt][br][bn + 1] = f2tf32(bv[i].y);
            Bs[nxt][br][bn + 2] = f2tf32(bv[i].z);
            Bs[nxt][br][bn + 3] = f2tf32(bv[i].w);
        }
        __syncthreads();
    }

    #pragma unroll
    for (int mt = 0; mt < 4; mt++) {
        const int m = m0 + wm * 64 + mt * 16 + g;
        #pragma unroll
        for (int nt = 0; nt < 4; nt++) {
            const int n = n0 + wn * 32 + nt * 8 + 2 * tig;
            *(float2*)(C + (long long)m * NN + n)       = make_float2(acc[mt][nt][0], acc[mt][nt][1]);
            *(float2*)(C + (long long)(m + 8) * NN + n) = make_float2(acc[mt][nt][2], acc[mt][nt][3]);
        }
    }
}

// ---------------------------------------------------------------------------
// context'[b,h,d,e] += sum_{n in split} exp(k[d,n]) * v[e,n]   (UNNORMALIZED)
// ksum[b,h*64+d]    += sum_{n in split} exp(k[d,n])
// exp without max subtraction: k ~ N(0,1), safe in fp32.
// ---------------------------------------------------------------------------
__global__ __launch_bounds__(256, 4) void context_kernel(
    const float* __restrict__ kv, float* __restrict__ ctx,
    float* __restrict__ ksum)
{
    const int h  = blockIdx.x;
    const int b  = blockIdx.y;
    const int sp = blockIdx.z;
    const float* Kp = kv + ((long long)b * 512 + h * 64) * 4096;
    const float* Vp = kv + ((long long)b * 512 + 256 + h * 64) * 4096;

    __shared__ float ks[64][65];
    __shared__ float vs[64][65];

    const int tid = threadIdx.x;
    const int ty = tid >> 4, tx = tid & 15;
    const int lrow = tid >> 4;
    const int lc4  = (tid & 15) * 4;

    float acc[4][4];
    #pragma unroll
    for (int i = 0; i < 4; i++)
        #pragma unroll
        for (int j = 0; j < 4; j++) acc[i][j] = 0.f;
    float rsum[4] = {0.f, 0.f, 0.f, 0.f};

    const int nbeg = sp * 256;
    for (int n0 = nbeg; n0 < nbeg + 256; n0 += 64) {
        __syncthreads();
        #pragma unroll
        for (int i = 0; i < 4; i++) {
            const int row = lrow + i * 16;
            float4 kvv = *(const float4*)(Kp + (long long)row * 4096 + n0 + lc4);
            float4 vv  = *(const float4*)(Vp + (long long)row * 4096 + n0 + lc4);
            float e0 = expf(kvv.x), e1 = expf(kvv.y), e2 = expf(kvv.z), e3 = expf(kvv.w);
            ks[row][lc4 + 0] = e0; ks[row][lc4 + 1] = e1;
            ks[row][lc4 + 2] = e2; ks[row][lc4 + 3] = e3;
            rsum[i] += (e0 + e1) + (e2 + e3);
            vs[row][lc4 + 0] = vv.x; vs[row][lc4 + 1] = vv.y;
            vs[row][lc4 + 2] = vv.z; vs[row][lc4 + 3] = vv.w;
        }
        __syncthreads();
        #pragma unroll 8
        for (int j = 0; j < 64; j++) {
            float a[4], bb[4];
            #pragma unroll
            for (int i = 0; i < 4; i++) a[i]  = ks[ty * 4 + i][j];
            #pragma unroll
            for (int i = 0; i < 4; i++) bb[i] = vs[tx * 4 + i][j];
            #pragma unroll
            for (int i = 0; i < 4; i++)
                #pragma unroll
                for (int e = 0; e < 4; e++)
                    acc[i][e] = fmaf(a[i], bb[e], acc[i][e]);
        }
    }

    // ksum: reduce across the 16 lanes sharing lrow, then atomic
    #pragma unroll
    for (int i = 0; i < 4; i++) {
        float s = rsum[i];
        s += __shfl_xor_sync(0xffffffffu, s, 1);
        s += __shfl_xor_sync(0xffffffffu, s, 2);
        s += __shfl_xor_sync(0xffffffffu, s, 4);
        s += __shfl_xor_sync(0xffffffffu, s, 8);
        if ((tid & 15) == 0)
            atomicAdd(&ksum[b * 256 + h * 64 + lrow + i * 16], s);
    }

    float* cbase = ctx + (long long)(b * 4 + h) * 64 * 64;
    #pragma unroll
    for (int i = 0; i < 4; i++)
        #pragma unroll
        for (int e = 0; e < 4; e++)
            atomicAdd(&cbase[(ty * 4 + i) * 64 + tx * 4 + e], acc[i][e]);
}

// ---------------------------------------------------------------------------
// W2[b][o, h*64+d] = (sum_e w_out[o, h*64+e] * ctx'[b,h,d,e]) / ksum[d]
// ---------------------------------------------------------------------------
__global__ __launch_bounds__(256) void w2_kernel(
    const float* __restrict__ ctx, const float* __restrict__ w_out,
    const float* __restrict__ ksum, float* __restrict__ w2)
{
    const int oc = blockIdx.x;
    const int h  = blockIdx.y;
    const int b  = blockIdx.z;

    __shared__ float wt[64][128];
    __shared__ float ct[64][64];
    __shared__ float sinv[64];

    const int tid = threadIdx.x;
    if (tid < 64) sinv[tid] = 1.f / ksum[b * 256 + h * 64 + tid];

    {
        const int o = tid >> 1;
        const int eb = (tid & 1) * 32;
        const float* wrow = w_out + (long long)(oc * 128 + o) * 256 + h * 64 + eb;
        #pragma unroll
        for (int j = 0; j < 8; j++) {
            float4 v = *(const float4*)(wrow + j * 4);
            wt[eb + j * 4 + 0][o] = v.x;
            wt[eb + j * 4 + 1][o] = v.y;
            wt[eb + j * 4 + 2][o] = v.z;
            wt[eb + j * 4 + 3][o] = v.w;
        }
    }
    {
        const int d  = tid >> 2;
        const int eb = (tid & 3) * 16;
        const float* crow = ctx + (long long)(b * 4 + h) * 4096 + d * 64 + eb;
        #pragma unroll
        for (int j = 0; j < 4; j++) {
            float4 v = *(const float4*)(crow + j * 4);
            ct[eb + j * 4 + 0][d] = v.x;
            ct[eb + j * 4 + 1][d] = v.y;
            ct[eb + j * 4 + 2][d] = v.z;
            ct[eb + j * 4 + 3][d] = v.w;
        }
    }
    __syncthreads();

    const int ty = tid >> 4, tx = tid & 15;
    float acc[8][4];
    #pragma unroll
    for (int i = 0; i < 8; i++)
        #pragma unroll
        for (int j = 0; j < 4; j++) acc[i][j] = 0.f;

    #pragma unroll 4
    for (int e = 0; e < 64; e++) {
        float4 w0 = *(const float4*)&wt[e][ty * 8];
        float4 w1 = *(const float4*)&wt[e][ty * 8 + 4];
        float4 c0 = *(const float4*)&ct[e][tx * 4];
        const float wv[8] = {w0.x, w0.y, w0.z, w0.w, w1.x, w1.y, w1.z, w1.w};
        const float cv[4] = {c0.x, c0.y, c0.z, c0.w};
        #pragma unroll
        for (int i = 0; i < 8; i++)
            #pragma unroll
            for (int j = 0; j < 4; j++)
                acc[i][j] = fmaf(wv[i], cv[j], acc[i][j]);
    }

    const float s0 = sinv[tx * 4 + 0], s1 = sinv[tx * 4 + 1];
    const float s2 = sinv[tx * 4 + 2], s3 = sinv[tx * 4 + 3];
    float* w2base = w2 + (long long)b * 65536 + h * 64 + tx * 4;
    #pragma unroll
    for (int i = 0; i < 8; i++) {
        const int o = oc * 128 + ty * 8 + i;
        *(float4*)(w2base + (long long)o * 256) =
            make_float4(acc[i][0] * s0, acc[i][1] * s1, acc[i][2] * s2, acc[i][3] * s3);
    }
}

// ---------------------------------------------------------------------------
// Fused q + out: per (b, 64-col n-tile):
//   Qraw = w_q(256x256) @ x[b][:, tile]   (tf32 mma, K=256)
//   softmax over d within each head, *0.125, q -> smem (tf32)
//   out  = W2[b](256x256) @ q + bias      (tf32 mma, K=256)
// q never touches DRAM. 8 warps as 4(m) x 2(n), warp tile 64x32.
// ---------------------------------------------------------------------------
#define AS_W 264   // 256 + 8  (stride % 32 == 8 for conflict-free frag loads)
#define QS_W 72    // 64 + 8

__global__ __launch_bounds__(256, 1) void fused_qout_kernel(
    const float* __restrict__ wq, const float* __restrict__ x,
    const float* __restrict__ w2, const float* __restrict__ bias,
    float* __restrict__ out)
{
    extern __shared__ unsigned smx[];
    unsigned* sAs = smx;                                // [2][16][AS_W]
    unsigned* sBs = smx + 2 * 16 * AS_W;                // [2][16][QS_W]
    unsigned* sQ  = smx + 2 * 16 * AS_W + 2 * 16 * QS_W; // [256][QS_W]

    const int n0 = blockIdx.x * 64;
    const int b  = blockIdx.y;
    const float* X  = x  + (long long)b * 256 * 4096;
    const float* W2 = w2 + (long long)b * 65536;

    const int tid  = threadIdx.x;
    const int lane = tid & 31, warp = tid >> 5;
    const int wm = warp >> 1, wn = warp & 1;     // 4 x 2 warp grid
    const int g  = lane >> 2, tig = lane & 3;

    const int arow = tid >> 2, ac = tid & 3;     // A: 4 chunks of 64 rows, 16-k slab
    const int brow = tid >> 4, bn = (tid & 15) * 4;  // B: 16 x 64

    float acc[4][4][4];
    float4 av[4], bv;

    // ================= Phase 1: Qraw = wq @ X-tile =================
    #pragma unroll
    for (int i = 0; i < 4; i++)
        #pragma unroll
        for (int j = 0; j < 4; j++)
            #pragma unroll
            for (int k = 0; k < 4; k++) acc[i][j][k] = 0.f;

    #pragma unroll
    for (int i = 0; i < 4; i++)
        av[i] = *(const float4*)(wq + (long long)(arow + 64 * i) * 256 + ac * 4);
    bv = *(const float4*)(X + (long long)brow * 4096 + n0 + bn);

    #pragma unroll
    for (int i = 0; i < 4; i++) {
        const int r = (arow + 64 * i) ^ (ac << 3);
        sAs[(4 * ac + 0) * AS_W + r] = f2tf32(av[i].x);
        sAs[(4 * ac + 1) * AS_W + r] = f2tf32(av[i].y);
        sAs[(4 * ac + 2) * AS_W + r] = f2tf32(av[i].z);
        sAs[(4 * ac + 3) * AS_W + r] = f2tf32(av[i].w);
    }
    sBs[brow * QS_W + bn + 0] = f2tf32(bv.x);
    sBs[brow * QS_W + bn + 1] = f2tf32(bv.y);
    sBs[brow * QS_W + bn + 2] = f2tf32(bv.z);
    sBs[brow * QS_W + bn + 3] = f2tf32(bv.w);
    __syncthreads();

    for (int k0 = 0; ; k0 += 16) {
        const int cur = (k0 >> 4) & 1;
        const bool more = (k0 + 16 < 256);
        if (more) {
            const int k1 = k0 + 16;
            #pragma unroll
            for (int i = 0; i < 4; i++)
                av[i] = *(const float4*)(wq + (long long)(arow + 64 * i) * 256 + k1 + ac * 4);
            bv = *(const float4*)(X + (long long)(k1 + brow) * 4096 + n0 + bn);
        }

        const unsigned* A0 = sAs + cur * 16 * AS_W;
        const unsigned* B0 = sBs + cur * 16 * QS_W;
        #pragma unroll
        for (int kk = 0; kk < 16; kk += 8) {
            unsigned a[4][4], bf[4][2];
            const int xr  = (kk >> 2) << 3;
            const int xr2 = xr + 8;
            #pragma unroll
            for (int mt = 0; mt < 4; mt++) {
                const int m = wm * 64 + mt * 16 + g;
                a[mt][0] = A0[(kk + tig    ) * AS_W + ((m    ) ^ xr )];
                a[mt][1] = A0[(kk + tig    ) * AS_W + ((m + 8) ^ xr )];
                a[mt][2] = A0[(kk + tig + 4) * AS_W + ((m    ) ^ xr2)];
                a[mt][3] = A0[(kk + tig + 4) * AS_W + ((m + 8) ^ xr2)];
            }
            #pragma unroll
            for (int nt = 0; nt < 4; nt++) {
                const int n = wn * 32 + nt * 8 + g;
                bf[nt][0] = B0[(kk + tig    ) * QS_W + n];
                bf[nt][1] = B0[(kk + tig + 4) * QS_W + n];
            }
            #pragma unroll
            for (int mt = 0; mt < 4; mt++)
                #pragma unroll
                for (int nt = 0; nt < 4; nt++)
                    mma8(acc[mt][nt], a[mt], bf[nt]);
        }

        if (!more) break;
        const int nxt = cur ^ 1;
        unsigned* A1 = sAs + nxt * 16 * AS_W;
        unsigned* B1 = sBs + nxt * 16 * QS_W;
        #pragma unroll
        for (int i = 0; i < 4; i++) {
            const int r = (arow + 64 * i) ^ (ac << 3);
            A1[(4 * ac + 0) * AS_W + r] = f2tf32(av[i].x);
            A1[(4 * ac + 1) * AS_W + r] = f2tf32(av[i].y);
            A1[(4 * ac + 2) * AS_W + r] = f2tf32(av[i].z);
            A1[(4 * ac + 3) * AS_W + r] = f2tf32(av[i].w);
        }
        B1[brow * QS_W + bn + 0] = f2tf32(bv.x);
        B1[brow * QS_W + bn + 1] = f2tf32(bv.y);
        B1[brow * QS_W + bn + 2] = f2tf32(bv.z);
        B1[brow * QS_W + bn + 3] = f2tf32(bv.w);
        __syncthreads();
    }

    // softmax over d (warp's 64 rows = head wm), *0.125
    #pragma unroll
    for (int nt = 0; nt < 4; nt++)
        #pragma unroll
        for (int c = 0; c < 2; c++) {
            float mx = -1e30f;
            #pragma unroll
            for (int mt = 0; mt < 4; mt++) {
                mx = fmaxf(mx, acc[mt][nt][c]);
                mx = fmaxf(mx, acc[mt][nt][c + 2]);
            }
            mx = fmaxf(mx, __shfl_xor_sync(0xffffffffu, mx, 4));
            mx = fmaxf(mx, __shfl_xor_sync(0xffffffffu, mx, 8));
            mx = fmaxf(mx, __shfl_xor_sync(0xffffffffu, mx, 16));
            float s = 0.f;
            #pragma unroll
            for (int mt = 0; mt < 4; mt++) {
                acc[mt][nt][c]     = expf(acc[mt][nt][c]     - mx);
                acc[mt][nt][c + 2] = expf(acc[mt][nt][c + 2] - mx);
                s += acc[mt][nt][c] + acc[mt][nt][c + 2];
            }
            s += __shfl_xor_sync(0xffffffffu, s, 4);
            s += __shfl_xor_sync(0xffffffffu, s, 8);
            s += __shfl_xor_sync(0xffffffffu, s, 16);
            const float r = 0.125f / s;
            #pragma unroll
            for (int mt = 0; mt < 4; mt++) {
                acc[mt][nt][c]     *= r;
                acc[mt][nt][c + 2] *= r;
            }
        }

    // park q in smem (tf32)
    #pragma unroll
    for (int mt = 0; mt < 4; mt++)
        #pragma unroll
        for (int nt = 0; nt < 4; nt++)
            #pragma unroll
            for (int c = 0; c < 4; c++) {
                const int m = wm * 64 + mt * 16 + g + ((c >= 2) ? 8 : 0);
                const int n = wn * 32 + nt * 8 + 2 * tig + (c & 1);
                sQ[m * QS_W + n] = f2tf32(acc[mt][nt][c]);
            }
    __syncthreads();

    // ================= Phase 2: out = W2 @ q + bias =================
    #pragma unroll
    for (int i = 0; i < 4; i++)
        #pragma unroll
        for (int j = 0; j < 4; j++)
            #pragma unroll
            for (int k = 0; k < 4; k++) acc[i][j][k] = 0.f;

    #pragma unroll
    for (int i = 0; i < 4; i++)
        av[i] = *(const float4*)(W2 + (long long)(arow + 64 * i) * 256 + ac * 4);
    #pragma unroll
    for (int i = 0; i < 4; i++) {
        const int r = (arow + 64 * i) ^ (ac << 3);
        sAs[(4 * ac + 0) * AS_W + r] = f2tf32(av[i].x);
        sAs[(4 * ac + 1) * AS_W + r] = f2tf32(av[i].y);
        sAs[(4 * ac + 2) * AS_W + r] = f2tf32(av[i].z);
        sAs[(4 * ac + 3) * AS_W + r] = f2tf32(av[i].w);
    }
    __syncthreads();

    for (int k0 = 0; ; k0 += 16) {
        const int cur = (k0 >> 4) & 1;
        const bool more = (k0 + 16 < 256);
        if (more) {
            const int k1 = k0 + 16;
            #pragma unroll
            for (int i = 0; i < 4; i++)
                av[i] = *(const float4*)(W2 + (long long)(arow + 64 * i) * 256 + k1 + ac * 4);
        }

        const unsigned* A0 = sAs + cur * 16 * AS_W;
        #pragma unroll
        for (int kk = 0; kk < 16; kk += 8) {
            unsigned a[4][4], bf[4][2];
            const int xr  = (kk >> 2) << 3;
            const int xr2 = xr + 8;
            #pragma unroll
            for (int mt = 0; mt < 4; mt++) {
                const int m = wm * 64 + mt * 16 + g;
                a[mt][0] = A0[(kk + tig    ) * AS_W + ((m    ) ^ xr )];
                a[mt][1] = A0[(kk + tig    ) * AS_W + ((m + 8) ^ xr )];
                a[mt][2] = A0[(kk + tig + 4) * AS_W + ((m    ) ^ xr2)];
                a[mt][3] = A0[(kk + tig + 4) * AS_W + ((m + 8) ^ xr2)];
            }
            #pragma unroll
            for (int nt = 0; nt < 4; nt++) {
                const int n = wn * 32 + nt * 8 + g;
                bf[nt][0] = sQ[(k0 + kk + tig    ) * QS_W + n];
                bf[nt][1] = sQ[(k0 + kk + tig + 4) * QS_W + n];
            }
            #pragma unroll
            for (int mt = 0; mt < 4; mt++)
                #pragma unroll
                for (int nt = 0; nt < 4; nt++)
                    mma8(acc[mt][nt], a[mt], bf[nt]);
        }

        if (!more) break;
        const int nxt = cur ^ 1;
        unsigned* A1 = sAs + nxt * 16 * AS_W;
        #pragma unroll
        for (int i = 0; i < 4; i++) {
            const int r = (arow + 64 * i) ^ (ac << 3);
            A1[(4 * ac + 0) * AS_W + r] = f2tf32(av[i].x);
            A1[(4 * ac + 1) * AS_W + r] = f2tf32(av[i].y);
            A1[(4 * ac + 2) * AS_W + r] = f2tf32(av[i].z);
            A1[(4 * ac + 3) * AS_W + r] = f2tf32(av[i].w);
        }
        __syncthreads();
    }

    float* O = out + (long long)b * 256 * 4096;
    #pragma unroll
    for (int mt = 0; mt < 4; mt++) {
        const int m = wm * 64 + mt * 16 + g;
        const float bb0 = bias[m];
        const float bb1 = bias[m + 8];
        #pragma unroll
        for (int nt = 0; nt < 4; nt++) {
            const int n = n0 + wn * 32 + nt * 8 + 2 * tig;
            *(float2*)(O + (long long)m * 4096 + n) =
                make_float2(acc[mt][nt][0] + bb0, acc[mt][nt][1] + bb0);
            *(float2*)(O + (long long)(m + 8) * 4096 + n) =
                make_float2(acc[mt][nt][2] + bb1, acc[mt][nt][3] + bb1);
        }
    }
}

static const int FUSED_SMEM = (2 * 16 * AS_W + 2 * 16 * QS_W + 256 * QS_W) * 4;

// ---------------------------------------------------------------------------
extern "C" void kernel_launch(void* const* d_in, const int* in_sizes, int n_in,
                              void* d_out, int out_size)
{
    const float *x = nullptr, *w_qkv = nullptr, *w_out = nullptr, *b_out = nullptr;
    for (int i = 0; i < n_in; i++) {
        switch (in_sizes[i]) {
            case 16 * 256 * 4096: x     = (const float*)d_in[i]; break;
            case 768 * 256:       w_qkv = (const float*)d_in[i]; break;
            case 256 * 256:       w_out = (const float*)d_in[i]; break;
            case 256:             b_out = (const float*)d_in[i]; break;
        }
    }
    float* out = (float*)d_out;

    float *kv, *ctx, *w2, *ksum;
    cudaGetSymbolAddress((void**)&kv,   g_kv);
    cudaGetSymbolAddress((void**)&ctx,  g_ctx);
    cudaGetSymbolAddress((void**)&w2,   g_w2);
    cudaGetSymbolAddress((void**)&ksum, g_ksum);

    cudaFuncSetAttribute(fused_qout_kernel,
                         cudaFuncAttributeMaxDynamicSharedMemorySize, FUSED_SMEM);

    // 1) kv[b] = w_qkv[256:768] @ x[b]   (512 x 4096, K=256) x16
    gemm_tf32_kernel<<<dim3(32, 4, 16), 256>>>(
        w_qkv + 256 * 256, 0LL, 256, x, 256LL * 4096, kv, 512LL * 4096, 256);

    // 2) unnormalized context + ksum (exp inline, no stats pass)
    cudaMemsetAsync(ctx, 0, 16 * 4 * 64 * 64 * sizeof(float));
    cudaMemsetAsync(ksum, 0, 16 * 256 * sizeof(float));
    context_kernel<<<dim3(4, 16, 16), 256>>>(kv, ctx, ksum);

    // 3) W2[b] = (w_out-slice @ ctx'^T) / ksum
    w2_kernel<<<dim3(2, 4, 16), 256>>>(ctx, w_out, ksum, w2);

    // 4) fused: q-gemm + q-softmax + out-gemm + bias (q stays in smem)
    fused_qout_kernel<<<dim3(64, 16), 256, FUSED_SMEM>>>(
        w_qkv, x, w2, b_out, out);
}

// round 7
// speedup vs baseline: 1.0667x; 1.0667x over previous
#include <cuda_runtime.h>

// Shapes: x (16,256,4096), w_qkv (768,256), w_out (256,256), b_out (256)
__device__ float g_kv[16LL * 512 * 4096];   // k (rows 0..255) and v (rows 256..511) per batch
__device__ float g_ctx[16 * 4 * 64 * 64];   // UNNORMALIZED context per (b, h)
__device__ float g_w2[16 * 256 * 256];      // fused (w_out x ctx / ksum) per batch
__device__ float g_ksum[16 * 256];          // per k-row sum of exp(k)

__device__ __forceinline__ unsigned f2tf32(float f) {
    unsigned u; asm("cvt.rna.tf32.f32 %0, %1;" : "=r"(u) : "f"(f)); return u;
}

__device__ __forceinline__ void mma8(float* c, const unsigned* a, const unsigned* b) {
    asm volatile(
        "mma.sync.aligned.m16n8k8.row.col.f32.tf32.tf32.f32 "
        "{%0,%1,%2,%3},{%4,%5,%6,%7},{%8,%9},{%0,%1,%2,%3};"
        : "+f"(c[0]), "+f"(c[1]), "+f"(c[2]), "+f"(c[3])
        : "r"(a[0]), "r"(a[1]), "r"(a[2]), "r"(a[3]), "r"(b[0]), "r"(b[1]));
}

#define SA 136

// ---------------------------------------------------------------------------
// TF32 GEMM for k,v: C[b] = A(M x K, lda) @ B[b](K x 4096)
// 128x128 tile, BK=16, double-buffered, 8 warps (2x4) of 64x32.
// ---------------------------------------------------------------------------
__global__ __launch_bounds__(256) void gemm_tf32_kernel(
    const float* __restrict__ A, long long strideA, int lda,
    const float* __restrict__ B, long long strideB,
    float* __restrict__ C, long long strideC, int Kdim)
{
    const int NN = 4096;
    const int n0 = blockIdx.x * 128;
    const int m0 = blockIdx.y * 128;
    const long long bz = blockIdx.z;
    A += bz * strideA;  B += bz * strideB;  C += bz * strideC;

    __shared__ unsigned As[2][16][SA];
    __shared__ unsigned Bs[2][16][SA];

    const int tid  = threadIdx.x;
    const int lane = tid & 31, warp = tid >> 5;
    const int wm = warp >> 2, wn = warp & 3;
    const int g  = lane >> 2, tig = lane & 3;

    const int arow = tid >> 2, ac = tid & 3;
    const int brow = tid >> 5, bn = (tid & 31) * 4;

    float acc[4][4][4];
    #pragma unroll
    for (int i = 0; i < 4; i++)
        #pragma unroll
        for (int j = 0; j < 4; j++)
            #pragma unroll
            for (int k = 0; k < 4; k++) acc[i][j][k] = 0.f;

    const float* Ap = A + (long long)m0 * lda;
    float4 av[2], bv[2];
    #pragma unroll
    for (int i = 0; i < 2; i++) {
        av[i] = *(const float4*)(Ap + (long long)(arow + 64 * i) * lda + ac * 4);
        bv[i] = *(const float4*)(B + (long long)(brow + 8 * i) * NN + n0 + bn);
    }
    #pragma unroll
    for (int i = 0; i < 2; i++) {
        const int r = (arow + 64 * i) ^ (ac << 3);
        As[0][4 * ac + 0][r] = f2tf32(av[i].x);
        As[0][4 * ac + 1][r] = f2tf32(av[i].y);
        As[0][4 * ac + 2][r] = f2tf32(av[i].z);
        As[0][4 * ac + 3][r] = f2tf32(av[i].w);
        const int br = brow + 8 * i;
        Bs[0][br][bn + 0] = f2tf32(bv[i].x);
        Bs[0][br][bn + 1] = f2tf32(bv[i].y);
        Bs[0][br][bn + 2] = f2tf32(bv[i].z);
        Bs[0][br][bn + 3] = f2tf32(bv[i].w);
    }
    __syncthreads();

    for (int k0 = 0; ; k0 += 16) {
        const int cur = (k0 >> 4) & 1;
        const bool more = (k0 + 16 < Kdim);
        if (more) {
            const int k1 = k0 + 16;
            #pragma unroll
            for (int i = 0; i < 2; i++) {
                av[i] = *(const float4*)(Ap + (long long)(arow + 64 * i) * lda + k1 + ac * 4);
                bv[i] = *(const float4*)(B + (long long)(k1 + brow + 8 * i) * NN + n0 + bn);
            }
        }

        #pragma unroll
        for (int kk = 0; kk < 16; kk += 8) {
            unsigned a[4][4], bf[4][2];
            const int xr  = (kk >> 2) << 3;
            const int xr2 = xr + 8;
            #pragma unroll
            for (int mt = 0; mt < 4; mt++) {
                const int m = wm * 64 + mt * 16 + g;
                a[mt][0] = As[cur][kk + tig    ][m       ^ xr ];
                a[mt][1] = As[cur][kk + tig    ][(m + 8) ^ xr ];
                a[mt][2] = As[cur][kk + tig + 4][m       ^ xr2];
                a[mt][3] = As[cur][kk + tig + 4][(m + 8) ^ xr2];
            }
            #pragma unroll
            for (int nt = 0; nt < 4; nt++) {
                const int n = wn * 32 + nt * 8 + g;
                bf[nt][0] = Bs[cur][kk + tig    ][n];
                bf[nt][1] = Bs[cur][kk + tig + 4][n];
            }
            #pragma unroll
            for (int mt = 0; mt < 4; mt++)
                #pragma unroll
                for (int nt = 0; nt < 4; nt++)
                    mma8(acc[mt][nt], a[mt], bf[nt]);
        }

        if (!more) break;

        const int nxt = cur ^ 1;
        #pragma unroll
        for (int i = 0; i < 2; i++) {
            const int r = (arow + 64 * i) ^ (ac << 3);
            As[nxt][4 * ac + 0][r] = f2tf32(av[i].x);
            As[nxt][4 * ac + 1][r] = f2tf32(av[i].y);
            As[nxt][4 * ac + 2][r] = f2tf32(av[i].z);
            As[nxt][4 * ac + 3][r] = f2tf32(av[i].w);
            const int br = brow + 8 * i;
            Bs[nxt][br][bn + 0] = f2tf32(bv[i].x);
            Bs[nxt][br][bn + 1] = f2tf32(bv[i].y);
            Bs[nxt][br][bn + 2] = f2tf32(bv[i].z);
            Bs[nxt][br][bn + 3] = f2tf32(bv[i].w);
        }
        __syncthreads();
    }

    #pragma unroll
    for (int mt = 0; mt < 4; mt++) {
        const int m = m0 + wm * 64 + mt * 16 + g;
        #pragma unroll
        for (int nt = 0; nt < 4; nt++) {
            const int n = n0 + wn * 32 + nt * 8 + 2 * tig;
            *(float2*)(C + (long long)m * NN + n)       = make_float2(acc[mt][nt][0], acc[mt][nt][1]);
            *(float2*)(C + (long long)(m + 8) * NN + n) = make_float2(acc[mt][nt][2], acc[mt][nt][3]);
        }
    }
}

// ---------------------------------------------------------------------------
// context'[b,h,d,e] += sum_{n in split} exp(k[d,n]) * v[e,n]   (UNNORMALIZED)
// ksum[b,h*64+d]    += sum_{n in split} exp(k[d,n])
// ---------------------------------------------------------------------------
__global__ __launch_bounds__(256, 4) void context_kernel(
    const float* __restrict__ kv, float* __restrict__ ctx,
    float* __restrict__ ksum)
{
    const int h  = blockIdx.x;
    const int b  = blockIdx.y;
    const int sp = blockIdx.z;
    const float* Kp = kv + ((long long)b * 512 + h * 64) * 4096;
    const float* Vp = kv + ((long long)b * 512 + 256 + h * 64) * 4096;

    __shared__ float ks[64][65];
    __shared__ float vs[64][65];

    const int tid = threadIdx.x;
    const int ty = tid >> 4, tx = tid & 15;
    const int lrow = tid >> 4;
    const int lc4  = (tid & 15) * 4;

    float acc[4][4];
    #pragma unroll
    for (int i = 0; i < 4; i++)
        #pragma unroll
        for (int j = 0; j < 4; j++) acc[i][j] = 0.f;
    float rsum[4] = {0.f, 0.f, 0.f, 0.f};

    const int nbeg = sp * 256;
    for (int n0 = nbeg; n0 < nbeg + 256; n0 += 64) {
        __syncthreads();
        #pragma unroll
        for (int i = 0; i < 4; i++) {
            const int row = lrow + i * 16;
            float4 kvv = *(const float4*)(Kp + (long long)row * 4096 + n0 + lc4);
            float4 vv  = *(const float4*)(Vp + (long long)row * 4096 + n0 + lc4);
            float e0 = expf(kvv.x), e1 = expf(kvv.y), e2 = expf(kvv.z), e3 = expf(kvv.w);
            ks[row][lc4 + 0] = e0; ks[row][lc4 + 1] = e1;
            ks[row][lc4 + 2] = e2; ks[row][lc4 + 3] = e3;
            rsum[i] += (e0 + e1) + (e2 + e3);
            vs[row][lc4 + 0] = vv.x; vs[row][lc4 + 1] = vv.y;
            vs[row][lc4 + 2] = vv.z; vs[row][lc4 + 3] = vv.w;
        }
        __syncthreads();
        #pragma unroll 8
        for (int j = 0; j < 64; j++) {
            float a[4], bb[4];
            #pragma unroll
            for (int i = 0; i < 4; i++) a[i]  = ks[ty * 4 + i][j];
            #pragma unroll
            for (int i = 0; i < 4; i++) bb[i] = vs[tx * 4 + i][j];
            #pragma unroll
            for (int i = 0; i < 4; i++)
                #pragma unroll
                for (int e = 0; e < 4; e++)
                    acc[i][e] = fmaf(a[i], bb[e], acc[i][e]);
        }
    }

    #pragma unroll
    for (int i = 0; i < 4; i++) {
        float s = rsum[i];
        s += __shfl_xor_sync(0xffffffffu, s, 1);
        s += __shfl_xor_sync(0xffffffffu, s, 2);
        s += __shfl_xor_sync(0xffffffffu, s, 4);
        s += __shfl_xor_sync(0xffffffffu, s, 8);
        if ((tid & 15) == 0)
            atomicAdd(&ksum[b * 256 + h * 64 + lrow + i * 16], s);
    }

    float* cbase = ctx + (long long)(b * 4 + h) * 64 * 64;
    #pragma unroll
    for (int i = 0; i < 4; i++)
        #pragma unroll
        for (int e = 0; e < 4; e++)
            atomicAdd(&cbase[(ty * 4 + i) * 64 + tx * 4 + e], acc[i][e]);
}

// ---------------------------------------------------------------------------
// W2[b][o, h*64+d] = (sum_e w_out[o, h*64+e] * ctx'[b,h,d,e]) / ksum[d]
// ---------------------------------------------------------------------------
__global__ __launch_bounds__(256) void w2_kernel(
    const float* __restrict__ ctx, const float* __restrict__ w_out,
    const float* __restrict__ ksum, float* __restrict__ w2)
{
    const int oc = blockIdx.x;
    const int h  = blockIdx.y;
    const int b  = blockIdx.z;

    __shared__ float wt[64][128];
    __shared__ float ct[64][64];
    __shared__ float sinv[64];

    const int tid = threadIdx.x;
    if (tid < 64) sinv[tid] = 1.f / ksum[b * 256 + h * 64 + tid];

    {
        const int o = tid >> 1;
        const int eb = (tid & 1) * 32;
        const float* wrow = w_out + (long long)(oc * 128 + o) * 256 + h * 64 + eb;
        #pragma unroll
        for (int j = 0; j < 8; j++) {
            float4 v = *(const float4*)(wrow + j * 4);
            wt[eb + j * 4 + 0][o] = v.x;
            wt[eb + j * 4 + 1][o] = v.y;
            wt[eb + j * 4 + 2][o] = v.z;
            wt[eb + j * 4 + 3][o] = v.w;
        }
    }
    {
        const int d  = tid >> 2;
        const int eb = (tid & 3) * 16;
        const float* crow = ctx + (long long)(b * 4 + h) * 4096 + d * 64 + eb;
        #pragma unroll
        for (int j = 0; j < 4; j++) {
            float4 v = *(const float4*)(crow + j * 4);
            ct[eb + j * 4 + 0][d] = v.x;
            ct[eb + j * 4 + 1][d] = v.y;
            ct[eb + j * 4 + 2][d] = v.z;
            ct[eb + j * 4 + 3][d] = v.w;
        }
    }
    __syncthreads();

    const int ty = tid >> 4, tx = tid & 15;
    float acc[8][4];
    #pragma unroll
    for (int i = 0; i < 8; i++)
        #pragma unroll
        for (int j = 0; j < 4; j++) acc[i][j] = 0.f;

    #pragma unroll 4
    for (int e = 0; e < 64; e++) {
        float4 w0 = *(const float4*)&wt[e][ty * 8];
        float4 w1 = *(const float4*)&wt[e][ty * 8 + 4];
        float4 c0 = *(const float4*)&ct[e][tx * 4];
        const float wv[8] = {w0.x, w0.y, w0.z, w0.w, w1.x, w1.y, w1.z, w1.w};
        const float cv[4] = {c0.x, c0.y, c0.z, c0.w};
        #pragma unroll
        for (int i = 0; i < 8; i++)
            #pragma unroll
            for (int j = 0; j < 4; j++)
                acc[i][j] = fmaf(wv[i], cv[j], acc[i][j]);
    }

    const float s0 = sinv[tx * 4 + 0], s1 = sinv[tx * 4 + 1];
    const float s2 = sinv[tx * 4 + 2], s3 = sinv[tx * 4 + 3];
    float* w2base = w2 + (long long)b * 65536 + h * 64 + tx * 4;
    #pragma unroll
    for (int i = 0; i < 8; i++) {
        const int o = oc * 128 + ty * 8 + i;
        *(float4*)(w2base + (long long)o * 256) =
            make_float4(acc[i][0] * s0, acc[i][1] * s1, acc[i][2] * s2, acc[i][3] * s3);
    }
}

// ---------------------------------------------------------------------------
// Fused q + out, 512 threads, 128-wide n-tile:
//   Qraw = w_q(256x256) @ x[b][:, tile]  -> softmax over d per head * 0.125
//   -> q parked tf32 in smem -> out = W2[b] @ q + bias
// 16 warps as 4(m) x 4(n), warp tile 64x32. q never touches DRAM.
// ---------------------------------------------------------------------------
#define AS_W 264   // 256 + 8
#define BS_W 136   // 128 + 8
#define QS_W 136

__global__ __launch_bounds__(512, 1) void fused_qout_kernel(
    const float* __restrict__ wq, const float* __restrict__ x,
    const float* __restrict__ w2, const float* __restrict__ bias,
    float* __restrict__ out)
{
    extern __shared__ unsigned smx[];
    unsigned* sAs = smx;                                 // [2][16][AS_W]
    unsigned* sBs = smx + 2 * 16 * AS_W;                 // [2][16][BS_W]
    unsigned* sQ  = smx + 2 * 16 * AS_W + 2 * 16 * BS_W; // [256][QS_W]

    const int n0 = blockIdx.x * 128;
    const int b  = blockIdx.y;
    const float* X  = x  + (long long)b * 256 * 4096;
    const float* W2 = w2 + (long long)b * 65536;

    const int tid  = threadIdx.x;
    const int lane = tid & 31, warp = tid >> 5;
    const int wm = warp >> 2, wn = warp & 3;      // 4 x 4 warp grid
    const int g  = lane >> 2, tig = lane & 3;

    const int arow = tid >> 1, ac8 = (tid & 1) * 8;  // A: 256 rows x 8 k each
    const int brow = tid >> 5, bn = lane * 4;        // B: 16 x 128

    float acc[4][4][4];
    float4 av0, av1, bv;

    // ================= Phase 1: Qraw = wq @ X-tile =================
    #pragma unroll
    for (int i = 0; i < 4; i++)
        #pragma unroll
        for (int j = 0; j < 4; j++)
            #pragma unroll
            for (int k = 0; k < 4; k++) acc[i][j][k] = 0.f;

    av0 = *(const float4*)(wq + (long long)arow * 256 + ac8);
    av1 = *(const float4*)(wq + (long long)arow * 256 + ac8 + 4);
    bv  = *(const float4*)(X + (long long)brow * 4096 + n0 + bn);

    {
        float a8[8] = {av0.x, av0.y, av0.z, av0.w, av1.x, av1.y, av1.z, av1.w};
        #pragma unroll
        for (int j = 0; j < 8; j++) {
            const int k = ac8 + j;
            sAs[k * AS_W + (arow ^ ((k >> 2) << 3))] = f2tf32(a8[j]);
        }
        sBs[brow * BS_W + bn + 0] = f2tf32(bv.x);
        sBs[brow * BS_W + bn + 1] = f2tf32(bv.y);
        sBs[brow * BS_W + bn + 2] = f2tf32(bv.z);
        sBs[brow * BS_W + bn + 3] = f2tf32(bv.w);
    }
    __syncthreads();

    for (int k0 = 0; ; k0 += 16) {
        const int cur = (k0 >> 4) & 1;
        const bool more = (k0 + 16 < 256);
        if (more) {
            const int k1 = k0 + 16;
            av0 = *(const float4*)(wq + (long long)arow * 256 + k1 + ac8);
            av1 = *(const float4*)(wq + (long long)arow * 256 + k1 + ac8 + 4);
            bv  = *(const float4*)(X + (long long)(k1 + brow) * 4096 + n0 + bn);
        }

        const unsigned* A0 = sAs + cur * 16 * AS_W;
        const unsigned* B0 = sBs + cur * 16 * BS_W;
        #pragma unroll
        for (int kk = 0; kk < 16; kk += 8) {
            unsigned a[4][4], bf[4][2];
            const int xr  = (kk >> 2) << 3;
            const int xr2 = xr + 8;
            #pragma unroll
            for (int mt = 0; mt < 4; mt++) {
                const int m = wm * 64 + mt * 16 + g;
                a[mt][0] = A0[(kk + tig    ) * AS_W + ((m    ) ^ xr )];
                a[mt][1] = A0[(kk + tig    ) * AS_W + ((m + 8) ^ xr )];
                a[mt][2] = A0[(kk + tig + 4) * AS_W + ((m    ) ^ xr2)];
                a[mt][3] = A0[(kk + tig + 4) * AS_W + ((m + 8) ^ xr2)];
            }
            #pragma unroll
            for (int nt = 0; nt < 4; nt++) {
                const int n = wn * 32 + nt * 8 + g;
                bf[nt][0] = B0[(kk + tig    ) * BS_W + n];
                bf[nt][1] = B0[(kk + tig + 4) * BS_W + n];
            }
            #pragma unroll
            for (int mt = 0; mt < 4; mt++)
                #pragma unroll
                for (int nt = 0; nt < 4; nt++)
                    mma8(acc[mt][nt], a[mt], bf[nt]);
        }

        if (!more) break;
        const int nxt = cur ^ 1;
        unsigned* A1 = sAs + nxt * 16 * AS_W;
        unsigned* B1 = sBs + nxt * 16 * BS_W;
        {
            float a8[8] = {av0.x, av0.y, av0.z, av0.w, av1.x, av1.y, av1.z, av1.w};
            #pragma unroll
            for (int j = 0; j < 8; j++) {
                const int k = ac8 + j;
                A1[k * AS_W + (arow ^ ((k >> 2) << 3))] = f2tf32(a8[j]);
            }
            B1[brow * BS_W + bn + 0] = f2tf32(bv.x);
            B1[brow * BS_W + bn + 1] = f2tf32(bv.y);
            B1[brow * BS_W + bn + 2] = f2tf32(bv.z);
            B1[brow * BS_W + bn + 3] = f2tf32(bv.w);
        }
        __syncthreads();
    }

    // softmax over d: warp wm owns exactly head wm (rows wm*64..wm*64+63)
    #pragma unroll
    for (int nt = 0; nt < 4; nt++)
        #pragma unroll
        for (int c = 0; c < 2; c++) {
            float mx = -1e30f;
            #pragma unroll
            for (int mt = 0; mt < 4; mt++) {
                mx = fmaxf(mx, acc[mt][nt][c]);
                mx = fmaxf(mx, acc[mt][nt][c + 2]);
            }
            mx = fmaxf(mx, __shfl_xor_sync(0xffffffffu, mx, 4));
            mx = fmaxf(mx, __shfl_xor_sync(0xffffffffu, mx, 8));
            mx = fmaxf(mx, __shfl_xor_sync(0xffffffffu, mx, 16));
            float s = 0.f;
            #pragma unroll
            for (int mt = 0; mt < 4; mt++) {
                acc[mt][nt][c]     = expf(acc[mt][nt][c]     - mx);
                acc[mt][nt][c + 2] = expf(acc[mt][nt][c + 2] - mx);
                s += acc[mt][nt][c] + acc[mt][nt][c + 2];
            }
            s += __shfl_xor_sync(0xffffffffu, s, 4);
            s += __shfl_xor_sync(0xffffffffu, s, 8);
            s += __shfl_xor_sync(0xffffffffu, s, 16);
            const float r = 0.125f / s;
            #pragma unroll
            for (int mt = 0; mt < 4; mt++) {
                acc[mt][nt][c]     *= r;
                acc[mt][nt][c + 2] *= r;
            }
        }

    // park q in smem (tf32): q[m][n], m = d-row (K of phase 2), n = column
    #pragma unroll
    for (int mt = 0; mt < 4; mt++)
        #pragma unroll
        for (int nt = 0; nt < 4; nt++)
            #pragma unroll
            for (int c = 0; c < 4; c++) {
                const int m = wm * 64 + mt * 16 + g + ((c >= 2) ? 8 : 0);
                const int n = wn * 32 + nt * 8 + 2 * tig + (c & 1);
                sQ[m * QS_W + n] = f2tf32(acc[mt][nt][c]);
            }
    __syncthreads();   // sQ complete; phase-1 buffers dead

    // ================= Phase 2: out = W2 @ q + bias =================
    #pragma unroll
    for (int i = 0; i < 4; i++)
        #pragma unroll
        for (int j = 0; j < 4; j++)
            #pragma unroll
            for (int k = 0; k < 4; k++) acc[i][j][k] = 0.f;

    av0 = *(const float4*)(W2 + (long long)arow * 256 + ac8);
    av1 = *(const float4*)(W2 + (long long)arow * 256 + ac8 + 4);
    {
        float a8[8] = {av0.x, av0.y, av0.z, av0.w, av1.x, av1.y, av1.z, av1.w};
        #pragma unroll
        for (int j = 0; j < 8; j++) {
            const int k = ac8 + j;
            sAs[k * AS_W + (arow ^ ((k >> 2) << 3))] = f2tf32(a8[j]);
        }
    }
    __syncthreads();

    for (int k0 = 0; ; k0 += 16) {
        const int cur = (k0 >> 4) & 1;
        const bool more = (k0 + 16 < 256);
        if (more) {
            const int k1 = k0 + 16;
            av0 = *(const float4*)(W2 + (long long)arow * 256 + k1 + ac8);
            av1 = *(const float4*)(W2 + (long long)arow * 256 + k1 + ac8 + 4);
        }

        const unsigned* A0 = sAs + cur * 16 * AS_W;
        #pragma unroll
        for (int kk = 0; kk < 16; kk += 8) {
            unsigned a[4][4], bf[4][2];
            const int xr  = (kk >> 2) << 3;
            const int xr2 = xr + 8;
            #pragma unroll
            for (int mt = 0; mt < 4; mt++) {
                const int m = wm * 64 + mt * 16 + g;
                a[mt][0] = A0[(kk + tig    ) * AS_W + ((m    ) ^ xr )];
                a[mt][1] = A0[(kk + tig    ) * AS_W + ((m + 8) ^ xr )];
                a[mt][2] = A0[(kk + tig + 4) * AS_W + ((m    ) ^ xr2)];
                a[mt][3] = A0[(kk + tig + 4) * AS_W + ((m + 8) ^ xr2)];
            }
            #pragma unroll
            for (int nt = 0; nt < 4; nt++) {
                const int n = wn * 32 + nt * 8 + g;
                bf[nt][0] = sQ[(k0 + kk + tig    ) * QS_W + n];
                bf[nt][1] = sQ[(k0 + kk + tig + 4) * QS_W + n];
            }
            #pragma unroll
            for (int mt = 0; mt < 4; mt++)
                #pragma unroll
                for (int nt = 0; nt < 4; nt++)
                    mma8(acc[mt][nt], a[mt], bf[nt]);
        }

        if (!more) break;
        const int nxt = cur ^ 1;
        unsigned* A1 = sAs + nxt * 16 * AS_W;
        {
            float a8[8] = {av0.x, av0.y, av0.z, av0.w, av1.x, av1.y, av1.z, av1.w};
            #pragma unroll
            for (int j = 0; j < 8; j++) {
                const int k = ac8 + j;
                A1[k * AS_W + (arow ^ ((k >> 2) << 3))] = f2tf32(a8[j]);
            }
        }
        __syncthreads();
    }

    float* O = out + (long long)b * 256 * 4096;
    #pragma unroll
    for (int mt = 0; mt < 4; mt++) {
        const int m = wm * 64 + mt * 16 + g;
        const float bb0 = bias[m];
        const float bb1 = bias[m + 8];
        #pragma unroll
        for (int nt = 0; nt < 4; nt++) {
            const int n = n0 + wn * 32 + nt * 8 + 2 * tig;
            *(float2*)(O + (long long)m * 4096 + n) =
                make_float2(acc[mt][nt][0] + bb0, acc[mt][nt][1] + bb0);
            *(float2*)(O + (long long)(m + 8) * 4096 + n) =
                make_float2(acc[mt][nt][2] + bb1, acc[mt][nt][3] + bb1);
        }
    }
}

static const int FUSED_SMEM = (2 * 16 * AS_W + 2 * 16 * BS_W + 256 * QS_W) * 4;

// ---------------------------------------------------------------------------
extern "C" void kernel_launch(void* const* d_in, const int* in_sizes, int n_in,
                              void* d_out, int out_size)
{
    const float *x = nullptr, *w_qkv = nullptr, *w_out = nullptr, *b_out = nullptr;
    for (int i = 0; i < n_in; i++) {
        switch (in_sizes[i]) {
            case 16 * 256 * 4096: x     = (const float*)d_in[i]; break;
            case 768 * 256:       w_qkv = (const float*)d_in[i]; break;
            case 256 * 256:       w_out = (const float*)d_in[i]; break;
            case 256:             b_out = (const float*)d_in[i]; break;
        }
    }
    float* out = (float*)d_out;

    float *kv, *ctx, *w2, *ksum;
    cudaGetSymbolAddress((void**)&kv,   g_kv);
    cudaGetSymbolAddress((void**)&ctx,  g_ctx);
    cudaGetSymbolAddress((void**)&w2,   g_w2);
    cudaGetSymbolAddress((void**)&ksum, g_ksum);

    cudaFuncSetAttribute(fused_qout_kernel,
                         cudaFuncAttributeMaxDynamicSharedMemorySize, FUSED_SMEM);

    // 1) kv[b] = w_qkv[256:768] @ x[b]   (512 x 4096, K=256) x16
    gemm_tf32_kernel<<<dim3(32, 4, 16), 256>>>(
        w_qkv + 256 * 256, 0LL, 256, x, 256LL * 4096, kv, 512LL * 4096, 256);

    // 2) unnormalized context + ksum (exp inline)
    cudaMemsetAsync(ctx, 0, 16 * 4 * 64 * 64 * sizeof(float));
    cudaMemsetAsync(ksum, 0, 16 * 256 * sizeof(float));
    context_kernel<<<dim3(4, 16, 16), 256>>>(kv, ctx, ksum);

    // 3) W2[b] = (w_out-slice @ ctx'^T) / ksum
    w2_kernel<<<dim3(2, 4, 16), 256>>>(ctx, w_out, ksum, w2);

    // 4) fused: q-gemm + q-softmax + out-gemm + bias (q stays in smem)
    fused_qout_kernel<<<dim3(32, 16), 512, FUSED_SMEM>>>(
        w_qkv, x, w2, b_out, out);
}

// round 8
// speedup vs baseline: 1.1430x; 1.0715x over previous
#include <cuda_runtime.h>

// Shapes: x (16,256,4096), w_qkv (768,256), w_out (256,256), b_out (256)
__device__ float g_qkv[16LL * 768 * 4096];  // q (softmaxed in epilogue), k RAW, v
__device__ float g_ctx[16 * 4 * 64 * 64];   // UNNORMALIZED context per (b, h)
__device__ float g_w2[16 * 256 * 256];      // (w_out x ctx / ksum) per batch
__device__ float g_ksum[16 * 256];          // per k-row sum of exp(k)

__device__ __forceinline__ unsigned f2tf32(float f) {
    unsigned u; asm("cvt.rna.tf32.f32 %0, %1;" : "=r"(u) : "f"(f)); return u;
}

__device__ __forceinline__ void mma8(float* c, const unsigned* a, const unsigned* b) {
    asm volatile(
        "mma.sync.aligned.m16n8k8.row.col.f32.tf32.tf32.f32 "
        "{%0,%1,%2,%3},{%4,%5,%6,%7},{%8,%9},{%0,%1,%2,%3};"
        : "+f"(c[0]), "+f"(c[1]), "+f"(c[2]), "+f"(c[3])
        : "r"(a[0]), "r"(a[1]), "r"(a[2]), "r"(a[3]), "r"(b[0]), "r"(b[1]));
}

#define SA 136

// ---------------------------------------------------------------------------
// TF32 tensor-core GEMM: C[b] = A[b](M x K, lda) @ B[b](K x 4096) [+bias]
// 128x128 block tile, BK=16, double-buffered smem, 8 warps of 64x32.
// If m0 < q_rows: fused softmax over the warp's 64 M-rows (one head) * 0.125.
// ---------------------------------------------------------------------------
__global__ __launch_bounds__(256) void gemm_tf32_kernel(
    const float* __restrict__ A, long long strideA, int lda,
    const float* __restrict__ B, long long strideB,
    float* __restrict__ C, long long strideC,
    int Kdim, const float* __restrict__ bias, int q_rows)
{
    const int NN = 4096;
    const int n0 = blockIdx.x * 128;
    const int m0 = blockIdx.y * 128;
    const long long bz = blockIdx.z;
    A += bz * strideA;  B += bz * strideB;  C += bz * strideC;

    __shared__ unsigned As[2][16][SA];
    __shared__ unsigned Bs[2][16][SA];

    const int tid  = threadIdx.x;
    const int lane = tid & 31, warp = tid >> 5;
    const int wm = warp >> 2, wn = warp & 3;
    const int g  = lane >> 2, tig = lane & 3;

    const int arow = tid >> 2, ac = tid & 3;
    const int brow = tid >> 5, bn = (tid & 31) * 4;

    float acc[4][4][4];
    #pragma unroll
    for (int i = 0; i < 4; i++)
        #pragma unroll
        for (int j = 0; j < 4; j++)
            #pragma unroll
            for (int k = 0; k < 4; k++) acc[i][j][k] = 0.f;

    const float* Ap = A + (long long)m0 * lda;
    float4 av[2], bv[2];
    #pragma unroll
    for (int i = 0; i < 2; i++) {
        av[i] = *(const float4*)(Ap + (long long)(arow + 64 * i) * lda + ac * 4);
        bv[i] = *(const float4*)(B + (long long)(brow + 8 * i) * NN + n0 + bn);
    }
    #pragma unroll
    for (int i = 0; i < 2; i++) {
        const int r = (arow + 64 * i) ^ (ac << 3);
        As[0][4 * ac + 0][r] = f2tf32(av[i].x);
        As[0][4 * ac + 1][r] = f2tf32(av[i].y);
        As[0][4 * ac + 2][r] = f2tf32(av[i].z);
        As[0][4 * ac + 3][r] = f2tf32(av[i].w);
        const int br = brow + 8 * i;
        Bs[0][br][bn + 0] = f2tf32(bv[i].x);
        Bs[0][br][bn + 1] = f2tf32(bv[i].y);
        Bs[0][br][bn + 2] = f2tf32(bv[i].z);
        Bs[0][br][bn + 3] = f2tf32(bv[i].w);
    }
    __syncthreads();

    for (int k0 = 0; ; k0 += 16) {
        const int cur = (k0 >> 4) & 1;
        const bool more = (k0 + 16 < Kdim);
        if (more) {
            const int k1 = k0 + 16;
            #pragma unroll
            for (int i = 0; i < 2; i++) {
                av[i] = *(const float4*)(Ap + (long long)(arow + 64 * i) * lda + k1 + ac * 4);
                bv[i] = *(const float4*)(B + (long long)(k1 + brow + 8 * i) * NN + n0 + bn);
            }
        }

        #pragma unroll
        for (int kk = 0; kk < 16; kk += 8) {
            unsigned a[4][4], bf[4][2];
            const int xr  = (kk >> 2) << 3;
            const int xr2 = xr + 8;
            #pragma unroll
            for (int mt = 0; mt < 4; mt++) {
                const int m = wm * 64 + mt * 16 + g;
                a[mt][0] = As[cur][kk + tig    ][m       ^ xr ];
                a[mt][1] = As[cur][kk + tig    ][(m + 8) ^ xr ];
                a[mt][2] = As[cur][kk + tig + 4][m       ^ xr2];
                a[mt][3] = As[cur][kk + tig + 4][(m + 8) ^ xr2];
            }
            #pragma unroll
            for (int nt = 0; nt < 4; nt++) {
                const int n = wn * 32 + nt * 8 + g;
                bf[nt][0] = Bs[cur][kk + tig    ][n];
                bf[nt][1] = Bs[cur][kk + tig + 4][n];
            }
            #pragma unroll
            for (int mt = 0; mt < 4; mt++)
                #pragma unroll
                for (int nt = 0; nt < 4; nt++)
                    mma8(acc[mt][nt], a[mt], bf[nt]);
        }

        if (!more) break;

        const int nxt = cur ^ 1;
        #pragma unroll
        for (int i = 0; i < 2; i++) {
            const int r = (arow + 64 * i) ^ (ac << 3);
            As[nxt][4 * ac + 0][r] = f2tf32(av[i].x);
            As[nxt][4 * ac + 1][r] = f2tf32(av[i].y);
            As[nxt][4 * ac + 2][r] = f2tf32(av[i].z);
            As[nxt][4 * ac + 3][r] = f2tf32(av[i].w);
            const int br = brow + 8 * i;
            Bs[nxt][br][bn + 0] = f2tf32(bv[i].x);
            Bs[nxt][br][bn + 1] = f2tf32(bv[i].y);
            Bs[nxt][br][bn + 2] = f2tf32(bv[i].z);
            Bs[nxt][br][bn + 3] = f2tf32(bv[i].w);
        }
        __syncthreads();
    }

    // fused q-softmax: warp's 64 M-rows are exactly one head; axis d == M dir.
    if (m0 < q_rows) {
        #pragma unroll
        for (int nt = 0; nt < 4; nt++)
            #pragma unroll
            for (int c = 0; c < 2; c++) {
                float mx = -1e30f;
                #pragma unroll
                for (int mt = 0; mt < 4; mt++) {
                    mx = fmaxf(mx, acc[mt][nt][c]);
                    mx = fmaxf(mx, acc[mt][nt][c + 2]);
                }
                mx = fmaxf(mx, __shfl_xor_sync(0xffffffffu, mx, 4));
                mx = fmaxf(mx, __shfl_xor_sync(0xffffffffu, mx, 8));
                mx = fmaxf(mx, __shfl_xor_sync(0xffffffffu, mx, 16));
                float s = 0.f;
                #pragma unroll
                for (int mt = 0; mt < 4; mt++) {
                    acc[mt][nt][c]     = expf(acc[mt][nt][c]     - mx);
                    acc[mt][nt][c + 2] = expf(acc[mt][nt][c + 2] - mx);
                    s += acc[mt][nt][c] + acc[mt][nt][c + 2];
                }
                s += __shfl_xor_sync(0xffffffffu, s, 4);
                s += __shfl_xor_sync(0xffffffffu, s, 8);
                s += __shfl_xor_sync(0xffffffffu, s, 16);
                const float r = 0.125f / s;   // SCALE = 64^-0.5
                #pragma unroll
                for (int mt = 0; mt < 4; mt++) {
                    acc[mt][nt][c]     *= r;
                    acc[mt][nt][c + 2] *= r;
                }
            }
    }

    #pragma unroll
    for (int mt = 0; mt < 4; mt++) {
        const int m = m0 + wm * 64 + mt * 16 + g;
        const float bb0 = bias ? bias[m]     : 0.f;
        const float bb1 = bias ? bias[m + 8] : 0.f;
        #pragma unroll
        for (int nt = 0; nt < 4; nt++) {
            const int n = n0 + wn * 32 + nt * 8 + 2 * tig;
            float2 v0 = make_float2(acc[mt][nt][0] + bb0, acc[mt][nt][1] + bb0);
            float2 v1 = make_float2(acc[mt][nt][2] + bb1, acc[mt][nt][3] + bb1);
            *(float2*)(C + (long long)m * NN + n)       = v0;
            *(float2*)(C + (long long)(m + 8) * NN + n) = v1;
        }
    }
}

// ---------------------------------------------------------------------------
// context'[b,h,d,e] += sum_{n in split} exp(k[d,n]) * v[e,n]   (UNNORMALIZED)
// ksum[b,h*64+d]    += sum_{n in split} exp(k[d,n])
// exp without max subtraction: k ~ N(0,1), safe in fp32.
// ---------------------------------------------------------------------------
__global__ __launch_bounds__(256, 4) void context_kernel(
    const float* __restrict__ qkv, float* __restrict__ ctx,
    float* __restrict__ ksum)
{
    const int h  = blockIdx.x;
    const int b  = blockIdx.y;
    const int sp = blockIdx.z;
    const float* Kp = qkv + ((long long)b * 768 + 256 + h * 64) * 4096;
    const float* Vp = qkv + ((long long)b * 768 + 512 + h * 64) * 4096;

    __shared__ float ks[64][65];
    __shared__ float vs[64][65];

    const int tid = threadIdx.x;
    const int ty = tid >> 4, tx = tid & 15;
    const int lrow = tid >> 4;
    const int lc4  = (tid & 15) * 4;

    float acc[4][4];
    #pragma unroll
    for (int i = 0; i < 4; i++)
        #pragma unroll
        for (int j = 0; j < 4; j++) acc[i][j] = 0.f;
    float rsum[4] = {0.f, 0.f, 0.f, 0.f};

    const int nbeg = sp * 256;
    for (int n0 = nbeg; n0 < nbeg + 256; n0 += 64) {
        __syncthreads();
        #pragma unroll
        for (int i = 0; i < 4; i++) {
            const int row = lrow + i * 16;
            float4 kvv = *(const float4*)(Kp + (long long)row * 4096 + n0 + lc4);
            float4 vv  = *(const float4*)(Vp + (long long)row * 4096 + n0 + lc4);
            float e0 = expf(kvv.x), e1 = expf(kvv.y), e2 = expf(kvv.z), e3 = expf(kvv.w);
            ks[row][lc4 + 0] = e0; ks[row][lc4 + 1] = e1;
            ks[row][lc4 + 2] = e2; ks[row][lc4 + 3] = e3;
            rsum[i] += (e0 + e1) + (e2 + e3);
            vs[row][lc4 + 0] = vv.x; vs[row][lc4 + 1] = vv.y;
            vs[row][lc4 + 2] = vv.z; vs[row][lc4 + 3] = vv.w;
        }
        __syncthreads();
        #pragma unroll 8
        for (int j = 0; j < 64; j++) {
            float a[4], bb[4];
            #pragma unroll
            for (int i = 0; i < 4; i++) a[i]  = ks[ty * 4 + i][j];
            #pragma unroll
            for (int i = 0; i < 4; i++) bb[i] = vs[tx * 4 + i][j];
            #pragma unroll
            for (int i = 0; i < 4; i++)
                #pragma unroll
                for (int e = 0; e < 4; e++)
                    acc[i][e] = fmaf(a[i], bb[e], acc[i][e]);
        }
    }

    #pragma unroll
    for (int i = 0; i < 4; i++) {
        float s = rsum[i];
        s += __shfl_xor_sync(0xffffffffu, s, 1);
        s += __shfl_xor_sync(0xffffffffu, s, 2);
        s += __shfl_xor_sync(0xffffffffu, s, 4);
        s += __shfl_xor_sync(0xffffffffu, s, 8);
        if ((tid & 15) == 0)
            atomicAdd(&ksum[b * 256 + h * 64 + lrow + i * 16], s);
    }

    float* cbase = ctx + (long long)(b * 4 + h) * 64 * 64;
    #pragma unroll
    for (int i = 0; i < 4; i++)
        #pragma unroll
        for (int e = 0; e < 4; e++)
            atomicAdd(&cbase[(ty * 4 + i) * 64 + tx * 4 + e], acc[i][e]);
}

// ---------------------------------------------------------------------------
// W2[b][o, h*64+d] = (sum_e w_out[o, h*64+e] * ctx'[b,h,d,e]) / ksum[d]
// ---------------------------------------------------------------------------
__global__ __launch_bounds__(256) void w2_kernel(
    const float* __restrict__ ctx, const float* __restrict__ w_out,
    const float* __restrict__ ksum, float* __restrict__ w2)
{
    const int oc = blockIdx.x;
    const int h  = blockIdx.y;
    const int b  = blockIdx.z;

    __shared__ float wt[64][128];
    __shared__ float ct[64][64];
    __shared__ float sinv[64];

    const int tid = threadIdx.x;
    if (tid < 64) sinv[tid] = 1.f / ksum[b * 256 + h * 64 + tid];

    {
        const int o = tid >> 1;
        const int eb = (tid & 1) * 32;
        const float* wrow = w_out + (long long)(oc * 128 + o) * 256 + h * 64 + eb;
        #pragma unroll
        for (int j = 0; j < 8; j++) {
            float4 v = *(const float4*)(wrow + j * 4);
            wt[eb + j * 4 + 0][o] = v.x;
            wt[eb + j * 4 + 1][o] = v.y;
            wt[eb + j * 4 + 2][o] = v.z;
            wt[eb + j * 4 + 3][o] = v.w;
        }
    }
    {
        const int d  = tid >> 2;
        const int eb = (tid & 3) * 16;
        const float* crow = ctx + (long long)(b * 4 + h) * 4096 + d * 64 + eb;
        #pragma unroll
        for (int j = 0; j < 4; j++) {
            float4 v = *(const float4*)(crow + j * 4);
            ct[eb + j * 4 + 0][d] = v.x;
            ct[eb + j * 4 + 1][d] = v.y;
            ct[eb + j * 4 + 2][d] = v.z;
            ct[eb + j * 4 + 3][d] = v.w;
        }
    }
    __syncthreads();

    const int ty = tid >> 4, tx = tid & 15;
    float acc[8][4];
    #pragma unroll
    for (int i = 0; i < 8; i++)
        #pragma unroll
        for (int j = 0; j < 4; j++) acc[i][j] = 0.f;

    #pragma unroll 4
    for (int e = 0; e < 64; e++) {
        float4 w0 = *(const float4*)&wt[e][ty * 8];
        float4 w1 = *(const float4*)&wt[e][ty * 8 + 4];
        float4 c0 = *(const float4*)&ct[e][tx * 4];
        const float wv[8] = {w0.x, w0.y, w0.z, w0.w, w1.x, w1.y, w1.z, w1.w};
        const float cv[4] = {c0.x, c0.y, c0.z, c0.w};
        #pragma unroll
        for (int i = 0; i < 8; i++)
            #pragma unroll
            for (int j = 0; j < 4; j++)
                acc[i][j] = fmaf(wv[i], cv[j], acc[i][j]);
    }

    const float s0 = sinv[tx * 4 + 0], s1 = sinv[tx * 4 + 1];
    const float s2 = sinv[tx * 4 + 2], s3 = sinv[tx * 4 + 3];
    float* w2base = w2 + (long long)b * 65536 + h * 64 + tx * 4;
    #pragma unroll
    for (int i = 0; i < 8; i++) {
        const int o = oc * 128 + ty * 8 + i;
        *(float4*)(w2base + (long long)o * 256) =
            make_float4(acc[i][0] * s0, acc[i][1] * s1, acc[i][2] * s2, acc[i][3] * s3);
    }
}

// ---------------------------------------------------------------------------
extern "C" void kernel_launch(void* const* d_in, const int* in_sizes, int n_in,
                              void* d_out, int out_size)
{
    const float *x = nullptr, *w_qkv = nullptr, *w_out = nullptr, *b_out = nullptr;
    for (int i = 0; i < n_in; i++) {
        switch (in_sizes[i]) {
            case 16 * 256 * 4096: x     = (const float*)d_in[i]; break;
            case 768 * 256:       w_qkv = (const float*)d_in[i]; break;
            case 256 * 256:       w_out = (const float*)d_in[i]; break;
            case 256:             b_out = (const float*)d_in[i]; break;
        }
    }
    float* out = (float*)d_out;

    float *qkv, *ctx, *w2, *ksum;
    cudaGetSymbolAddress((void**)&qkv,  g_qkv);
    cudaGetSymbolAddress((void**)&ctx,  g_ctx);
    cudaGetSymbolAddress((void**)&w2,   g_w2);
    cudaGetSymbolAddress((void**)&ksum, g_ksum);

    // 1) qkv[b] = w_qkv @ x[b]; q-softmax fused into epilogue for rows < 256
    gemm_tf32_kernel<<<dim3(32, 6, 16), 256>>>(
        w_qkv, 0LL, 256, x, 256LL * 4096, qkv, 768LL * 4096, 256, nullptr, 256);

    // 2) unnormalized context + ksum (exp inline; no kstats pass)
    cudaMemsetAsync(ctx, 0, 16 * 4 * 64 * 64 * sizeof(float));
    cudaMemsetAsync(ksum, 0, 16 * 256 * sizeof(float));
    context_kernel<<<dim3(4, 16, 16), 256>>>(qkv, ctx, ksum);

    // 3) W2[b] = (w_out-slice @ ctx'^T) / ksum
    w2_kernel<<<dim3(2, 4, 16), 256>>>(ctx, w_out, ksum, w2);

    // 4) out[b] = W2[b] @ q[b] + b_out
    gemm_tf32_kernel<<<dim3(32, 2, 16), 256>>>(
        w2, 256LL * 256, 256, qkv, 768LL * 4096, out, 256LL * 4096, 256, b_out, 0);
}